// round 3
// baseline (speedup 1.0000x reference)
#include <cuda_runtime.h>

#define HW   96
#define LDP  100      // padded row stride (floats)

typedef unsigned long long ull;

__device__ __forceinline__ void ffma2(ull& d, ull a, ull b) {
    asm("fma.rn.f32x2 %0, %1, %2, %0;" : "+l"(d) : "l"(a), "l"(b));
}
__device__ __forceinline__ ull dup2(float a) {
    ull r; asm("mov.b64 %0, {%1, %1};" : "=l"(r) : "f"(a)); return r;
}
__device__ __forceinline__ float2 unpk(ull v) {
    float2 f; asm("mov.b64 {%0, %1}, %2;" : "=f"(f.x), "=f"(f.y) : "l"(v)); return f;
}
__device__ __forceinline__ ull pk2(float x, float y) {
    ull r; asm("mov.b64 %0, {%1, %2};" : "=l"(r) : "f"(x), "f"(y)); return r;
}

// Uniform GEMM inner loop: acc[3][6] (f32x2 pairs), A scalar (stride AST per k,
// warp-broadcast), B packed rows at Bbase + k*LDP + jq (LDS.128, conflict-free).
#define GEMM_CORE(A0p, A1p, A2p, AST, Bp, jq)                                   \
  do {                                                                          \
    _Pragma("unroll")                                                           \
    for (int r = 0; r < 3; r++)                                                 \
      _Pragma("unroll")                                                         \
      for (int pp = 0; pp < 6; pp++) acc[r][pp] = 0ULL;                         \
    _Pragma("unroll 2")                                                         \
    for (int k = 0; k < HW; k++) {                                              \
      ull ad0 = dup2((A0p)[k * (AST)]);                                         \
      ull ad1 = dup2((A1p)[k * (AST)]);                                         \
      ull ad2 = dup2((A2p)[k * (AST)]);                                         \
      const float* br = (Bp) + k * LDP + (jq);                                  \
      ulonglong2 b0 = *(const ulonglong2*)(br);                                 \
      ulonglong2 b1 = *(const ulonglong2*)(br + 32);                            \
      ulonglong2 b2 = *(const ulonglong2*)(br + 64);                            \
      ffma2(acc[0][0], ad0, b0.x); ffma2(acc[0][1], ad0, b0.y);                 \
      ffma2(acc[0][2], ad0, b1.x); ffma2(acc[0][3], ad0, b1.y);                 \
      ffma2(acc[0][4], ad0, b2.x); ffma2(acc[0][5], ad0, b2.y);                 \
      ffma2(acc[1][0], ad1, b0.x); ffma2(acc[1][1], ad1, b0.y);                 \
      ffma2(acc[1][2], ad1, b1.x); ffma2(acc[1][3], ad1, b1.y);                 \
      ffma2(acc[1][4], ad1, b2.x); ffma2(acc[1][5], ad1, b2.y);                 \
      ffma2(acc[2][0], ad2, b0.x); ffma2(acc[2][1], ad2, b0.y);                 \
      ffma2(acc[2][2], ad2, b1.x); ffma2(acc[2][3], ad2, b1.y);                 \
      ffma2(acc[2][4], ad2, b2.x); ffma2(acc[2][5], ad2, b2.y);                 \
    }                                                                           \
  } while (0)

__global__ void __launch_bounds__(256, 1)
axial_attn_kernel(const float* __restrict__ gq, const float* __restrict__ gk,
                  const float* __restrict__ gv, const float* __restrict__ gkh,
                  const float* __restrict__ gkw, float* __restrict__ gout, int C)
{
    extern __shared__ float sm[];
    float* sQ  = sm;                  // 96 x 100  Q[i][w]
    float* sK  = sQ  + HW * LDP;      // 96 x 100  K[j][w]
    float* sKT = sK  + HW * LDP;      // 96 x 100  K^T[w][j]
    float* sV  = sKT + HW * LDP;      // 96 x 100  V[j][w] (later V1[h][w])
    float* sA  = sV  + HW * LDP;      // 96 x 100  A1[i][j] (later A2^T[j][w])
    float* sKH = sA  + HW * LDP;      // 16
    float* sKW = sKH + 16;            // 16

    const int tid = threadIdx.x;
    const int tx  = tid & 7;          // 8 column-groups
    const int ty  = tid >> 3;         // 32 row-groups
    const int i0  = ty * 3;           // 3 rows per thread
    const int jq  = 4 * tx;           // quad base; cols = jq + 32p + e

    const int slice = blockIdx.x;
    const int c = slice - (slice / C) * C;
    const size_t base = (size_t)slice * (HW * HW);
    const float4* q4 = (const float4*)(gq + base);
    const float4* k4 = (const float4*)(gk + base);
    const float4* v4 = (const float4*)(gv + base);

    // ---- Stage 0: load Q, K, V (float4, coalesced) + kernel taps ----------
    #pragma unroll
    for (int f = tid; f < HW * HW / 4; f += 256) {
        int row = f / (HW / 4);
        int col = (f - row * (HW / 4)) * 4;
        int so  = row * LDP + col;
        *(float4*)(sQ + so) = q4[f];
        *(float4*)(sK + so) = k4[f];
        *(float4*)(sV + so) = v4[f];
    }
    if (tid < 13) {
        sKH[tid] = gkh[c * 13 + tid];
        sKW[tid] = gkw[c * 13 + tid];
    }
    __syncthreads();

    // ---- Transpose K -> KT (conflict-free both sides) ---------------------
    #pragma unroll
    for (int t = tid; t < HW * (HW / 4); t += 256) {
        int j  = t % HW;          // consecutive lanes -> consecutive rows j
        int w4 = t / HW;
        float4 kv = *(const float4*)(sK + j * LDP + 4 * w4);
        sKT[(4 * w4 + 0) * LDP + j] = kv.x;
        sKT[(4 * w4 + 1) * LDP + j] = kv.y;
        sKT[(4 * w4 + 2) * LDP + j] = kv.z;
        sKT[(4 * w4 + 3) * LDP + j] = kv.w;
    }
    __syncthreads();

    ull acc[3][6];

    // ============ GEMM 1: S1[i][j] = sum_w Q[i][w] * KT[w][j] ==============
    GEMM_CORE(sQ + (i0 + 0) * LDP, sQ + (i0 + 1) * LDP, sQ + (i0 + 2) * LDP, 1,
              sKT, jq);

    // ---- Softmax over j (per row i) + band_h; A1 -> sA row-major ----------
    #pragma unroll
    for (int r = 0; r < 3; r++) {
        float f[12];
        #pragma unroll
        for (int p = 0; p < 3; p++)
            #pragma unroll
            for (int hh = 0; hh < 2; hh++) {
                float2 t = unpk(acc[r][2 * p + hh]);
                f[4 * p + 2 * hh + 0] = t.x;
                f[4 * p + 2 * hh + 1] = t.y;
            }
        float m = f[0];
        #pragma unroll
        for (int e = 1; e < 12; e++) m = fmaxf(m, f[e]);
        #pragma unroll
        for (int off = 4; off >= 1; off >>= 1)
            m = fmaxf(m, __shfl_xor_sync(0xffffffffu, m, off));
        float s = 0.f;
        #pragma unroll
        for (int e = 0; e < 12; e++) { f[e] = __expf(f[e] - m); s += f[e]; }
        #pragma unroll
        for (int off = 4; off >= 1; off >>= 1)
            s += __shfl_xor_sync(0xffffffffu, s, off);
        float inv = 1.0f / s;
        const int i = i0 + r;
        #pragma unroll
        for (int e = 0; e < 12; e += 2) {
            int j  = jq + 32 * (e >> 2) + (e & 3);
            int b0 = j - i + 6;
            int b1 = j + 1 - i + 6;
            float v0 = fmaf(f[e],     inv, (b0 >= 0 && b0 < 13) ? sKH[b0] : 0.f);
            float v1 = fmaf(f[e + 1], inv, (b1 >= 0 && b1 < 13) ? sKH[b1] : 0.f);
            *(ull*)(sA + i * LDP + j) = pk2(v0, v1);
        }
    }
    __syncthreads();

    // ============ GEMM 2: V1[i][w] = sum_j A1[i][j] * V[j][w] ==============
    GEMM_CORE(sA + (i0 + 0) * LDP, sA + (i0 + 1) * LDP, sA + (i0 + 2) * LDP, 1,
              sV, jq);
    __syncthreads();   // all reads of sA / sV complete

    // store V1 into sV (packed pairs)
    #pragma unroll
    for (int r = 0; r < 3; r++)
        #pragma unroll
        for (int p = 0; p < 3; p++)
            #pragma unroll
            for (int hh = 0; hh < 2; hh++)
                *(ull*)(sV + (i0 + r) * LDP + jq + 32 * p + 2 * hh) =
                    acc[r][2 * p + hh];

    // ============ GEMM 3: S2[w][j] = sum_h Q[h][w] * K[h][j] ===============
    GEMM_CORE(sQ + (i0 + 0), sQ + (i0 + 1), sQ + (i0 + 2), LDP,
              sK, jq);

    // ---- Softmax over j (per row w) + band_w; A2^T -> sA ------------------
    #pragma unroll
    for (int r = 0; r < 3; r++) {
        float f[12];
        #pragma unroll
        for (int p = 0; p < 3; p++)
            #pragma unroll
            for (int hh = 0; hh < 2; hh++) {
                float2 t = unpk(acc[r][2 * p + hh]);
                f[4 * p + 2 * hh + 0] = t.x;
                f[4 * p + 2 * hh + 1] = t.y;
            }
        float m = f[0];
        #pragma unroll
        for (int e = 1; e < 12; e++) m = fmaxf(m, f[e]);
        #pragma unroll
        for (int off = 4; off >= 1; off >>= 1)
            m = fmaxf(m, __shfl_xor_sync(0xffffffffu, m, off));
        float s = 0.f;
        #pragma unroll
        for (int e = 0; e < 12; e++) { f[e] = __expf(f[e] - m); s += f[e]; }
        #pragma unroll
        for (int off = 4; off >= 1; off >>= 1)
            s += __shfl_xor_sync(0xffffffffu, s, off);
        float inv = 1.0f / s;
        const int w = i0 + r;
        #pragma unroll
        for (int e = 0; e < 12; e++) {
            int j  = jq + 32 * (e >> 2) + (e & 3);
            int bo = j - w + 6;
            float band = (bo >= 0 && bo < 13) ? sKW[bo] : 0.f;
            sA[j * LDP + w] = fmaf(f[e], inv, band);   // transposed store
        }
    }
    __syncthreads();   // V1 and A2^T visible

    // ============ GEMM 4: Out[h][w] = sum_j V1[h][j] * A2T[j][w] ===========
    GEMM_CORE(sV + (i0 + 0) * LDP, sV + (i0 + 1) * LDP, sV + (i0 + 2) * LDP, 1,
              sA, jq);

    // ---- Store Out (packed pairs, coalesced in 64B groups) ----------------
    float* op = gout + base;
    #pragma unroll
    for (int r = 0; r < 3; r++)
        #pragma unroll
        for (int p = 0; p < 3; p++)
            #pragma unroll
            for (int hh = 0; hh < 2; hh++)
                *(ull*)(op + (i0 + r) * HW + jq + 32 * p + 2 * hh) =
                    acc[r][2 * p + hh];
}

extern "C" void kernel_launch(void* const* d_in, const int* in_sizes, int n_in,
                              void* d_out, int out_size)
{
    const float* q  = (const float*)d_in[0];
    const float* k  = (const float*)d_in[1];
    const float* v  = (const float*)d_in[2];
    const float* kh = (const float*)d_in[3];
    const float* kw = (const float*)d_in[4];
    float* out = (float*)d_out;

    const int slices = in_sizes[0] / (HW * HW);   // B*C = 2048
    const int C      = in_sizes[3] / 13;          // 256

    const int smem_bytes = (5 * HW * LDP + 32) * (int)sizeof(float);  // 192128 B
    cudaFuncSetAttribute(axial_attn_kernel,
                         cudaFuncAttributeMaxDynamicSharedMemorySize, smem_bytes);

    axial_attn_kernel<<<slices, 256, smem_bytes>>>(q, k, v, kh, kw, out, C);
}

// round 7
// speedup vs baseline: 1.8268x; 1.8268x over previous
#include <cuda_runtime.h>
#include <cuda_bf16.h>

typedef unsigned int u32;
typedef unsigned long long ull;

#define HW   96
#define TPB  256
#define LDB  104              // bf16 elems per tile row (stride 208 B)
#define RSB  (LDB * 2)        // 208 bytes
#define TILE_B (HW * RSB)     // 19968 B per tile

// ---- smem byte offsets ----
#define OFF_KH   0            // 13 floats
#define OFF_KW   64           // 13 floats
#define OFF_RMAX 128          // 96*4 floats = 1536 B
#define OFF_RSUM (OFF_RMAX + 1536)
#define T_BASE   (OFF_RSUM + 1536)   // 3200
#define T_QH   (T_BASE + 0 * TILE_B)
#define T_QL   (T_BASE + 1 * TILE_B)
#define T_KH   (T_BASE + 2 * TILE_B)
#define T_KL   (T_BASE + 3 * TILE_B)
#define T_VH   (T_BASE + 4 * TILE_B)
#define T_VL   (T_BASE + 5 * TILE_B)
#define T_A1H  (T_BASE + 6 * TILE_B)
#define T_A1L  (T_BASE + 7 * TILE_B)
#define T_A2H  (T_BASE + 8 * TILE_B)
#define T_A2L  (T_BASE + 9 * TILE_B)
#define SMEM_TOTAL (T_BASE + 10 * TILE_B)   // 202880 B
// V1 reuses V tiles after GEMM2:
#define T_V1H T_VH
#define T_V1L T_VL

// ---------------- PTX wrappers ----------------
__device__ __forceinline__ u32 s2u(const void* p) {
    u32 a;
    asm("{ .reg .u64 t; cvta.to.shared.u64 t, %1; cvt.u32.u64 %0, t; }" : "=r"(a) : "l"(p));
    return a;
}
template<int TR>
__device__ __forceinline__ void ldsm4(u32 addr, u32* r) {
    if (TR)
        asm volatile("ldmatrix.sync.aligned.m8n8.x4.trans.shared.b16 {%0,%1,%2,%3}, [%4];"
                     : "=r"(r[0]), "=r"(r[1]), "=r"(r[2]), "=r"(r[3]) : "r"(addr));
    else
        asm volatile("ldmatrix.sync.aligned.m8n8.x4.shared.b16 {%0,%1,%2,%3}, [%4];"
                     : "=r"(r[0]), "=r"(r[1]), "=r"(r[2]), "=r"(r[3]) : "r"(addr));
}
template<int TR>
__device__ __forceinline__ void ldsm2(u32 addr, u32* r) {
    if (TR)
        asm volatile("ldmatrix.sync.aligned.m8n8.x2.trans.shared.b16 {%0,%1}, [%2];"
                     : "=r"(r[0]), "=r"(r[1]) : "r"(addr));
    else
        asm volatile("ldmatrix.sync.aligned.m8n8.x2.shared.b16 {%0,%1}, [%2];"
                     : "=r"(r[0]), "=r"(r[1]) : "r"(addr));
}
__device__ __forceinline__ void mma16816(float* c, const u32* a, const u32* b) {
    asm volatile("mma.sync.aligned.m16n8k16.row.col.f32.bf16.bf16.f32 "
                 "{%0,%1,%2,%3}, {%4,%5,%6,%7}, {%8,%9}, {%0,%1,%2,%3};"
                 : "+f"(c[0]), "+f"(c[1]), "+f"(c[2]), "+f"(c[3])
                 : "r"(a[0]), "r"(a[1]), "r"(a[2]), "r"(a[3]), "r"(b[0]), "r"(b[1]));
}

// ---- hi/lo bf16 split: pack pair (x0,x1) -> hi u32, lo u32 ----
__device__ __forceinline__ void cvt2(float x0, float x1, u32& h, u32& l) {
    __nv_bfloat16 h0 = __float2bfloat16(x0), h1 = __float2bfloat16(x1);
    float r0 = x0 - __bfloat162float(h0), r1 = x1 - __bfloat162float(h1);
    __nv_bfloat16 l0 = __float2bfloat16(r0), l1 = __float2bfloat16(r1);
    h = (u32)__bfloat16_as_ushort(h0) | ((u32)__bfloat16_as_ushort(h1) << 16);
    l = (u32)__bfloat16_as_ushort(l0) | ((u32)__bfloat16_as_ushort(l1) << 16);
}

// ---------------- GEMM: 96x96x96, warp tile 48x24, BF16x3 split ----------------
// TA/TB: operand accessed transposed (via ldmatrix.trans) from row-major tile.
template<int TA, int TB>
__device__ __forceinline__ void do_gemm(float acc[3][3][4],
                                        u32 aH, u32 aL, u32 bH, u32 bL,
                                        int m0, int n0, int lane)
{
    #pragma unroll
    for (int mt = 0; mt < 3; mt++)
        #pragma unroll
        for (int nt = 0; nt < 3; nt++)
            #pragma unroll
            for (int e = 0; e < 4; e++) acc[mt][nt][e] = 0.f;

    #pragma unroll 2
    for (int kk = 0; kk < HW; kk += 16) {
        u32 Ah[3][4], Al[3][4];
        #pragma unroll
        for (int mt = 0; mt < 3; mt++) {
            int m = m0 + mt * 16;
            int r, c;
            if (TA) { r = kk + (lane & 7) + ((lane >> 4) & 1) * 8; c = m  + ((lane >> 3) & 1) * 8; }
            else    { r = m  + (lane & 7) + ((lane >> 3) & 1) * 8; c = kk + ((lane >> 4) & 1) * 8; }
            u32 ad = (u32)(r * RSB + c * 2);
            ldsm4<TA>(aH + ad, Ah[mt]);
            ldsm4<TA>(aL + ad, Al[mt]);
        }
        u32 Bh[3][2], Bl[3][2];
        {   // x4 covers n-tiles 0,1
            int r, c;
            if (TB) { r = kk + (lane & 7) + ((lane >> 3) & 1) * 8; c = n0 + ((lane >> 4) & 1) * 8; }
            else    { r = n0 + (lane & 7) + ((lane >> 4) & 1) * 8; c = kk + ((lane >> 3) & 1) * 8; }
            u32 ad = (u32)(r * RSB + c * 2);
            u32 t[4];
            ldsm4<TB>(bH + ad, t);
            Bh[0][0] = t[0]; Bh[0][1] = t[1]; Bh[1][0] = t[2]; Bh[1][1] = t[3];
            ldsm4<TB>(bL + ad, t);
            Bl[0][0] = t[0]; Bl[0][1] = t[1]; Bl[1][0] = t[2]; Bl[1][1] = t[3];
        }
        {   // x2 covers n-tile 2
            int L = lane & 15;
            int r, c;
            if (TB) { r = kk + (L & 7) + ((L >> 3) & 1) * 8; c = n0 + 16; }
            else    { r = n0 + 16 + (L & 7); c = kk + ((L >> 3) & 1) * 8; }
            u32 ad = (u32)(r * RSB + c * 2);
            ldsm2<TB>(bH + ad, Bh[2]);
            ldsm2<TB>(bL + ad, Bl[2]);
        }
        #pragma unroll
        for (int mt = 0; mt < 3; mt++)
            #pragma unroll
            for (int nt = 0; nt < 3; nt++) {
                mma16816(acc[mt][nt], Ah[mt], Bh[nt]);
                mma16816(acc[mt][nt], Ah[mt], Bl[nt]);
                mma16816(acc[mt][nt], Al[mt], Bh[nt]);
            }
    }
}

// ---------------- softmax over fragment rows + band add -> bf16 hi/lo tile ----
__device__ __forceinline__ void softmax_ep(float acc[3][3][4], char* sm,
                                           int m0, int n0, const float* band,
                                           u32 outH, u32 outL, int lane, int wn)
{
    float* RMAX = (float*)(sm + OFF_RMAX);
    float* RSUM = (float*)(sm + OFF_RSUM);

    // 1) row max: quad-reduce, cross-warp via smem
    #pragma unroll
    for (int mt = 0; mt < 3; mt++)
        #pragma unroll
        for (int rh = 0; rh < 2; rh++) {
            float v = -1e30f;
            #pragma unroll
            for (int nt = 0; nt < 3; nt++)
                v = fmaxf(v, fmaxf(acc[mt][nt][2 * rh], acc[mt][nt][2 * rh + 1]));
            v = fmaxf(v, __shfl_xor_sync(0xffffffffu, v, 1));
            v = fmaxf(v, __shfl_xor_sync(0xffffffffu, v, 2));
            if ((lane & 3) == 0) {
                int row = m0 + mt * 16 + (lane >> 2) + 8 * rh;
                RMAX[row * 4 + wn] = v;
            }
        }
    __syncthreads();

    // 2) exp + row sum
    float inv[3][2];
    #pragma unroll
    for (int mt = 0; mt < 3; mt++)
        #pragma unroll
        for (int rh = 0; rh < 2; rh++) {
            int row = m0 + mt * 16 + (lane >> 2) + 8 * rh;
            const float* rm = RMAX + row * 4;
            float gm = fmaxf(fmaxf(rm[0], rm[1]), fmaxf(rm[2], rm[3]));
            float s = 0.f;
            #pragma unroll
            for (int nt = 0; nt < 3; nt++)
                #pragma unroll
                for (int e = 0; e < 2; e++) {
                    float ev = __expf(acc[mt][nt][2 * rh + e] - gm);
                    acc[mt][nt][2 * rh + e] = ev;
                    s += ev;
                }
            s += __shfl_xor_sync(0xffffffffu, s, 1);
            s += __shfl_xor_sync(0xffffffffu, s, 2);
            if ((lane & 3) == 0) RSUM[row * 4 + wn] = s;
            inv[mt][rh] = 0.f;   // placeholder
        }
    __syncthreads();

    #pragma unroll
    for (int mt = 0; mt < 3; mt++)
        #pragma unroll
        for (int rh = 0; rh < 2; rh++) {
            int row = m0 + mt * 16 + (lane >> 2) + 8 * rh;
            const float* rs = RSUM + row * 4;
            inv[mt][rh] = 1.0f / (rs[0] + rs[1] + rs[2] + rs[3]);
        }

    // 3) normalize + band, convert hi/lo, store pairs
    #pragma unroll
    for (int mt = 0; mt < 3; mt++)
        #pragma unroll
        for (int rh = 0; rh < 2; rh++) {
            int row = m0 + mt * 16 + (lane >> 2) + 8 * rh;
            #pragma unroll
            for (int nt = 0; nt < 3; nt++) {
                int col = n0 + nt * 8 + (lane & 3) * 2;
                u32 b0 = (u32)(col - row + 6), b1 = (u32)(col + 1 - row + 6);
                float x0 = fmaf(acc[mt][nt][2 * rh + 0], inv[mt][rh], b0 < 13u ? band[b0] : 0.f);
                float x1 = fmaf(acc[mt][nt][2 * rh + 1], inv[mt][rh], b1 < 13u ? band[b1] : 0.f);
                u32 h, l;
                cvt2(x0, x1, h, l);
                u32 ad = (u32)(row * RSB + col * 2);
                *(u32*)(sm + 0) = *(u32*)(sm + 0);   // no-op barrier for compiler? (removed below)
                ((u32*)0)[0] = 0;                     // NEVER REACHED – placeholder
            }
        }
}

__global__ void __launch_bounds__(TPB, 1)
axial_attn_hmma(const float* __restrict__ gq, const float* __restrict__ gk,
                const float* __restrict__ gv, const float* __restrict__ gkh,
                const float* __restrict__ gkw, float* __restrict__ gout, int C)
{
    extern __shared__ char sm[];
    const u32 sb = s2u(sm);
    const int tid  = threadIdx.x;
    const int lane = tid & 31;
    const int wid  = tid >> 5;
    const int wm   = wid >> 2;        // 0..1
    const int wn   = wid & 3;         // 0..3
    const int m0   = wm * 48;
    const int n0   = wn * 24;

    const int slice = blockIdx.x;
    const int c = slice - (slice / C) * C;
    const size_t base = (size_t)slice * (HW * HW);

    if (tid < 13) {
        ((float*)(sm + OFF_KH))[tid] = gkh[c * 13 + tid];
        ((float*)(sm + OFF_KW))[tid] = gkw[c * 13 + tid];
    }

    // ---- load + hi/lo convert Q, K, V (row-major, stride 104 bf16) ----
    const float4* q4 = (const float4*)(gq + base);
    const float4* k4 = (const float4*)(gk + base);
    const float4* v4 = (const float4*)(gv + base);
    #pragma unroll
    for (int it = 0; it < 9; it++) {
        int idx = tid + it * TPB;               // 0..2303
        int r   = idx / 24;
        int c4  = (idx - r * 24) * 4;
        u32 ad  = (u32)(r * RSB + c4 * 2);
        u32 h0, l0, h1, l1;
        float4 x;
        x = q4[idx];
        cvt2(x.x, x.y, h0, l0); cvt2(x.z, x.w, h1, l1);
        *(ull*)(sm + T_QH + ad) = (ull)h0 | ((ull)h1 << 32);
        *(ull*)(sm + T_QL + ad) = (ull)l0 | ((ull)l1 << 32);
        x = k4[idx];
        cvt2(x.x, x.y, h0, l0); cvt2(x.z, x.w, h1, l1);
        *(ull*)(sm + T_KH + ad) = (ull)h0 | ((ull)h1 << 32);
        *(ull*)(sm + T_KL + ad) = (ull)l0 | ((ull)l1 << 32);
        x = v4[idx];
        cvt2(x.x, x.y, h0, l0); cvt2(x.z, x.w, h1, l1);
        *(ull*)(sm + T_VH + ad) = (ull)h0 | ((ull)h1 << 32);
        *(ull*)(sm + T_VL + ad) = (ull)l0 | ((ull)l1 << 32);
    }
    __syncthreads();

    float acc[3][3][4];
    float* RMAX = (float*)(sm + OFF_RMAX);
    float* RSUM = (float*)(sm + OFF_RSUM);

    // =========== GEMM1: S1[i][j] = sum_w Q[i][w] K[j][w]  (A norm, B norm) ====
    do_gemm<0, 0>(acc, sb + T_QH, sb + T_QL, sb + T_KH, sb + T_KL, m0, n0, lane);

    // softmax rows i + band_h -> A1 tiles
    {
        const float* band = (const float*)(sm + OFF_KH);
        #pragma unroll
        for (int mt = 0; mt < 3; mt++)
            #pragma unroll
            for (int rh = 0; rh < 2; rh++) {
                float v = -1e30f;
                #pragma unroll
                for (int nt = 0; nt < 3; nt++)
                    v = fmaxf(v, fmaxf(acc[mt][nt][2 * rh], acc[mt][nt][2 * rh + 1]));
                v = fmaxf(v, __shfl_xor_sync(0xffffffffu, v, 1));
                v = fmaxf(v, __shfl_xor_sync(0xffffffffu, v, 2));
                if ((lane & 3) == 0)
                    RMAX[(m0 + mt * 16 + (lane >> 2) + 8 * rh) * 4 + wn] = v;
            }
        __syncthreads();
        float inv[3][2];
        #pragma unroll
        for (int mt = 0; mt < 3; mt++)
            #pragma unroll
            for (int rh = 0; rh < 2; rh++) {
                int row = m0 + mt * 16 + (lane >> 2) + 8 * rh;
                const float* rm = RMAX + row * 4;
                float gm = fmaxf(fmaxf(rm[0], rm[1]), fmaxf(rm[2], rm[3]));
                float s = 0.f;
                #pragma unroll
                for (int nt = 0; nt < 3; nt++)
                    #pragma unroll
                    for (int e = 0; e < 2; e++) {
                        float ev = __expf(acc[mt][nt][2 * rh + e] - gm);
                        acc[mt][nt][2 * rh + e] = ev;
                        s += ev;
                    }
                s += __shfl_xor_sync(0xffffffffu, s, 1);
                s += __shfl_xor_sync(0xffffffffu, s, 2);
                if ((lane & 3) == 0) RSUM[row * 4 + wn] = s;
                inv[mt][rh] = 0.f;
            }
        __syncthreads();
        #pragma unroll
        for (int mt = 0; mt < 3; mt++)
            #pragma unroll
            for (int rh = 0; rh < 2; rh++) {
                int row = m0 + mt * 16 + (lane >> 2) + 8 * rh;
                const float* rs = RSUM + row * 4;
                inv[mt][rh] = 1.0f / (rs[0] + rs[1] + rs[2] + rs[3]);
            }
        #pragma unroll
        for (int mt = 0; mt < 3; mt++)
            #pragma unroll
            for (int rh = 0; rh < 2; rh++) {
                int row = m0 + mt * 16 + (lane >> 2) + 8 * rh;
                #pragma unroll
                for (int nt = 0; nt < 3; nt++) {
                    int col = n0 + nt * 8 + (lane & 3) * 2;
                    u32 b0 = (u32)(col - row + 6), b1 = (u32)(col + 1 - row + 6);
                    float x0 = fmaf(acc[mt][nt][2 * rh + 0], inv[mt][rh], b0 < 13u ? band[b0] : 0.f);
                    float x1 = fmaf(acc[mt][nt][2 * rh + 1], inv[mt][rh], b1 < 13u ? band[b1] : 0.f);
                    u32 h, l;
                    cvt2(x0, x1, h, l);
                    u32 ad = (u32)(row * RSB + col * 2);
                    *(u32*)(sm + T_A1H + ad) = h;
                    *(u32*)(sm + T_A1L + ad) = l;
                }
            }
    }
    __syncthreads();

    // =========== GEMM3: S2[w][j] = sum_h Q[h][w] K[h][j]  (A trans, B trans) ==
    do_gemm<1, 1>(acc, sb + T_QH, sb + T_QL, sb + T_KH, sb + T_KL, m0, n0, lane);

    // softmax rows w + band_w -> A2 tiles
    {
        const float* band = (const float*)(sm + OFF_KW);
        #pragma unroll
        for (int mt = 0; mt < 3; mt++)
            #pragma unroll
            for (int rh = 0; rh < 2; rh++) {
                float v = -1e30f;
                #pragma unroll
                for (int nt = 0; nt < 3; nt++)
                    v = fmaxf(v, fmaxf(acc[mt][nt][2 * rh], acc[mt][nt][2 * rh + 1]));
                v = fmaxf(v, __shfl_xor_sync(0xffffffffu, v, 1));
                v = fmaxf(v, __shfl_xor_sync(0xffffffffu, v, 2));
                if ((lane & 3) == 0)
                    RMAX[(m0 + mt * 16 + (lane >> 2) + 8 * rh) * 4 + wn] = v;
            }
        __syncthreads();
        float inv[3][2];
        #pragma unroll
        for (int mt = 0; mt < 3; mt++)
            #pragma unroll
            for (int rh = 0; rh < 2; rh++) {
                int row = m0 + mt * 16 + (lane >> 2) + 8 * rh;
                const float* rm = RMAX + row * 4;
                float gm = fmaxf(fmaxf(rm[0], rm[1]), fmaxf(rm[2], rm[3]));
                float s = 0.f;
                #pragma unroll
                for (int nt = 0; nt < 3; nt++)
                    #pragma unroll
                    for (int e = 0; e < 2; e++) {
                        float ev = __expf(acc[mt][nt][2 * rh + e] - gm);
                        acc[mt][nt][2 * rh + e] = ev;
                        s += ev;
                    }
                s += __shfl_xor_sync(0xffffffffu, s, 1);
                s += __shfl_xor_sync(0xffffffffu, s, 2);
                if ((lane & 3) == 0) RSUM[row * 4 + wn] = s;
                inv[mt][rh] = 0.f;
            }
        __syncthreads();
        #pragma unroll
        for (int mt = 0; mt < 3; mt++)
            #pragma unroll
            for (int rh = 0; rh < 2; rh++) {
                int row = m0 + mt * 16 + (lane >> 2) + 8 * rh;
                const float* rs = RSUM + row * 4;
                inv[mt][rh] = 1.0f / (rs[0] + rs[1] + rs[2] + rs[3]);
            }
        #pragma unroll
        for (int mt = 0; mt < 3; mt++)
            #pragma unroll
            for (int rh = 0; rh < 2; rh++) {
                int row = m0 + mt * 16 + (lane >> 2) + 8 * rh;   // row = w
                #pragma unroll
                for (int nt = 0; nt < 3; nt++) {
                    int col = n0 + nt * 8 + (lane & 3) * 2;      // col = j
                    u32 b0 = (u32)(col - row + 6), b1 = (u32)(col + 1 - row + 6);
                    float x0 = fmaf(acc[mt][nt][2 * rh + 0], inv[mt][rh], b0 < 13u ? band[b0] : 0.f);
                    float x1 = fmaf(acc[mt][nt][2 * rh + 1], inv[mt][rh], b1 < 13u ? band[b1] : 0.f);
                    u32 h, l;
                    cvt2(x0, x1, h, l);
                    u32 ad = (u32)(row * RSB + col * 2);
                    *(u32*)(sm + T_A2H + ad) = h;
                    *(u32*)(sm + T_A2L + ad) = l;
                }
            }
    }
    __syncthreads();

    // =========== GEMM2: V1[i][w] = sum_j A1[i][j] V[j][w]  (A norm, B trans) ==
    do_gemm<0, 1>(acc, sb + T_A1H, sb + T_A1L, sb + T_VH, sb + T_VL, m0, n0, lane);
    __syncthreads();   // all reads of V complete before overwrite

    #pragma unroll
    for (int mt = 0; mt < 3; mt++)
        #pragma unroll
        for (int rh = 0; rh < 2; rh++) {
            int row = m0 + mt * 16 + (lane >> 2) + 8 * rh;
            #pragma unroll
            for (int nt = 0; nt < 3; nt++) {
                int col = n0 + nt * 8 + (lane & 3) * 2;
                u32 h, l;
                cvt2(acc[mt][nt][2 * rh + 0], acc[mt][nt][2 * rh + 1], h, l);
                u32 ad = (u32)(row * RSB + col * 2);
                *(u32*)(sm + T_V1H + ad) = h;
                *(u32*)(sm + T_V1L + ad) = l;
            }
        }
    __syncthreads();

    // =========== GEMM4: Out[h][w] = sum_j V1[h][j] A2[w][j]  (norm, norm) =====
    do_gemm<0, 0>(acc, sb + T_V1H, sb + T_V1L, sb + T_A2H, sb + T_A2L, m0, n0, lane);

    float* op = gout + base;
    #pragma unroll
    for (int mt = 0; mt < 3; mt++)
        #pragma unroll
        for (int rh = 0; rh < 2; rh++) {
            int row = m0 + mt * 16 + (lane >> 2) + 8 * rh;
            #pragma unroll
            for (int nt = 0; nt < 3; nt++) {
                int col = n0 + nt * 8 + (lane & 3) * 2;
                *(float2*)(op + row * HW + col) =
                    make_float2(acc[mt][nt][2 * rh + 0], acc[mt][nt][2 * rh + 1]);
            }
        }
}

extern "C" void kernel_launch(void* const* d_in, const int* in_sizes, int n_in,
                              void* d_out, int out_size)
{
    const float* q  = (const float*)d_in[0];
    const float* k  = (const float*)d_in[1];
    const float* v  = (const float*)d_in[2];
    const float* kh = (const float*)d_in[3];
    const float* kw = (const float*)d_in[4];
    float* out = (float*)d_out;

    const int slices = in_sizes[0] / (HW * HW);   // B*C = 2048
    const int C      = in_sizes[3] / 13;          // 256

    cudaFuncSetAttribute(axial_attn_hmma,
                         cudaFuncAttributeMaxDynamicSharedMemorySize, SMEM_TOTAL);
    axial_attn_hmma<<<slices, TPB, SMEM_TOTAL>>>(q, k, v, kh, kw, out, C);
}

// round 9
// speedup vs baseline: 2.0946x; 1.1466x over previous
#include <cuda_runtime.h>
#include <cuda_bf16.h>

typedef unsigned int u32;
typedef unsigned long long ull;

#define HW   96
#define TPB  384
#define LDB  104              // bf16 elems per tile row (stride 208 B, conflict-free ldmatrix)
#define RSB  (LDB * 2)        // 208 bytes
#define TILE_B (HW * RSB)     // 19968 B per tile

// ---- smem byte offsets ----
#define OFF_KH   0            // 13 floats
#define OFF_KW   64           // 13 floats
#define T_BASE   128
#define T_QH   (T_BASE + 0 * TILE_B)
#define T_QL   (T_BASE + 1 * TILE_B)
#define T_KH   (T_BASE + 2 * TILE_B)
#define T_KL   (T_BASE + 3 * TILE_B)
#define T_VH   (T_BASE + 4 * TILE_B)
#define T_VL   (T_BASE + 5 * TILE_B)
#define T_A1H  (T_BASE + 6 * TILE_B)
#define T_A1L  (T_BASE + 7 * TILE_B)
#define T_A2H  (T_BASE + 8 * TILE_B)
#define T_A2L  (T_BASE + 9 * TILE_B)
#define SMEM_TOTAL (T_BASE + 10 * TILE_B)   // 199808 B
// V1 reuses Q tiles (Q dead after GEMM3):
#define T_V1H T_QH
#define T_V1L T_QL

// ---------------- PTX wrappers ----------------
__device__ __forceinline__ u32 s2u(const void* p) {
    u32 a;
    asm("{ .reg .u64 t; cvta.to.shared.u64 t, %1; cvt.u32.u64 %0, t; }" : "=r"(a) : "l"(p));
    return a;
}
template<int TR>
__device__ __forceinline__ void ldsm4(u32 addr, u32* r) {
    if (TR)
        asm volatile("ldmatrix.sync.aligned.m8n8.x4.trans.shared.b16 {%0,%1,%2,%3}, [%4];"
                     : "=r"(r[0]), "=r"(r[1]), "=r"(r[2]), "=r"(r[3]) : "r"(addr));
    else
        asm volatile("ldmatrix.sync.aligned.m8n8.x4.shared.b16 {%0,%1,%2,%3}, [%4];"
                     : "=r"(r[0]), "=r"(r[1]), "=r"(r[2]), "=r"(r[3]) : "r"(addr));
}
__device__ __forceinline__ void mma16816(float* c, const u32* a, const u32* b) {
    asm volatile("mma.sync.aligned.m16n8k16.row.col.f32.bf16.bf16.f32 "
                 "{%0,%1,%2,%3}, {%4,%5,%6,%7}, {%8,%9}, {%0,%1,%2,%3};"
                 : "+f"(c[0]), "+f"(c[1]), "+f"(c[2]), "+f"(c[3])
                 : "r"(a[0]), "r"(a[1]), "r"(a[2]), "r"(a[3]), "r"(b[0]), "r"(b[1]));
}

// ---- hi/lo bf16 split: pack pair (x0,x1) -> hi u32, lo u32 ----
__device__ __forceinline__ void cvt2(float x0, float x1, u32& h, u32& l) {
    __nv_bfloat16 h0 = __float2bfloat16(x0), h1 = __float2bfloat16(x1);
    float r0 = x0 - __bfloat162float(h0), r1 = x1 - __bfloat162float(h1);
    __nv_bfloat16 l0 = __float2bfloat16(r0), l1 = __float2bfloat16(r1);
    h = (u32)__bfloat16_as_ushort(h0) | ((u32)__bfloat16_as_ushort(h1) << 16);
    l = (u32)__bfloat16_as_ushort(l0) | ((u32)__bfloat16_as_ushort(l1) << 16);
}

// ---------------- warp-tile GEMM: 16 x (8*NT) x 96, BF16x3 split ----------------
// TA/TB: operand accessed transposed via ldmatrix.trans from row-major tile.
// acc += Ah*Bh + Al*Bh + Ah*Bl   (B regs reused between hi and lo passes)
template<int TA, int TB, int NT>
__device__ __forceinline__ void gemm_wt(float acc[NT][4],
                                        u32 aH, u32 aL, u32 bH, u32 bL,
                                        int m0, int n0, int lane)
{
    #pragma unroll
    for (int nt = 0; nt < NT; nt++)
        #pragma unroll
        for (int e = 0; e < 4; e++) acc[nt][e] = 0.f;

    #pragma unroll
    for (int kk = 0; kk < HW; kk += 16) {
        int ra, ca;
        if (TA) { ra = kk + (lane & 7) + ((lane >> 4) & 1) * 8; ca = m0 + ((lane >> 3) & 1) * 8; }
        else    { ra = m0 + (lane & 7) + ((lane >> 3) & 1) * 8; ca = kk + ((lane >> 4) & 1) * 8; }
        const u32 aad = (u32)(ra * RSB + ca * 2);
        u32 Ah[4], Al[4];
        ldsm4<TA>(aH + aad, Ah);
        ldsm4<TA>(aL + aad, Al);

        u32 bad[NT / 2];
        #pragma unroll
        for (int p = 0; p < NT / 2; p++) {
            int rb, cb;
            if (TB) { rb = kk + (lane & 7) + ((lane >> 3) & 1) * 8; cb = n0 + p * 16 + ((lane >> 4) & 1) * 8; }
            else    { rb = n0 + p * 16 + (lane & 7) + ((lane >> 4) & 1) * 8; cb = kk + ((lane >> 3) & 1) * 8; }
            bad[p] = (u32)(rb * RSB + cb * 2);
        }

        u32 B[NT][2];
        #pragma unroll
        for (int p = 0; p < NT / 2; p++) {
            u32 t[4];
            ldsm4<TB>(bH + bad[p], t);
            B[2 * p][0] = t[0]; B[2 * p][1] = t[1];
            B[2 * p + 1][0] = t[2]; B[2 * p + 1][1] = t[3];
        }
        #pragma unroll
        for (int nt = 0; nt < NT; nt++) mma16816(acc[nt], Ah, B[nt]);
        #pragma unroll
        for (int nt = 0; nt < NT; nt++) mma16816(acc[nt], Al, B[nt]);
        #pragma unroll
        for (int p = 0; p < NT / 2; p++) {
            u32 t[4];
            ldsm4<TB>(bL + bad[p], t);
            B[2 * p][0] = t[0]; B[2 * p][1] = t[1];
            B[2 * p + 1][0] = t[2]; B[2 * p + 1][1] = t[3];
        }
        #pragma unroll
        for (int nt = 0; nt < NT; nt++) mma16816(acc[nt], Ah, B[nt]);
    }
}

__global__ void __launch_bounds__(TPB, 1)
axial_attn_hmma2(const float* __restrict__ gq, const float* __restrict__ gk,
                 const float* __restrict__ gv, const float* __restrict__ gkh,
                 const float* __restrict__ gkw, float* __restrict__ gout, int C)
{
    extern __shared__ char sm[];
    const u32 sb = s2u(sm);
    const int tid  = threadIdx.x;
    const int lane = tid & 31;
    const int wid  = tid >> 5;        // 0..11

    const int slice = blockIdx.x;
    const int c = slice - (slice / C) * C;
    const size_t base = (size_t)slice * (HW * HW);

    if (tid < 13) {
        ((float*)(sm + OFF_KH))[tid] = gkh[c * 13 + tid];
        ((float*)(sm + OFF_KW))[tid] = gkw[c * 13 + tid];
    }

    // ---- load + hi/lo convert Q, K, V (row-major, stride 104 bf16) ----
    const float4* q4 = (const float4*)(gq + base);
    const float4* k4 = (const float4*)(gk + base);
    const float4* v4 = (const float4*)(gv + base);
    #pragma unroll
    for (int it = 0; it < 6; it++) {
        int idx = tid + it * TPB;               // 0..2303
        int r   = idx / 24;
        int c4  = (idx - r * 24) * 4;
        u32 ad  = (u32)(r * RSB + c4 * 2);
        u32 h0, l0, h1, l1;
        float4 x;
        x = q4[idx];
        cvt2(x.x, x.y, h0, l0); cvt2(x.z, x.w, h1, l1);
        *(ull*)(sm + T_QH + ad) = (ull)h0 | ((ull)h1 << 32);
        *(ull*)(sm + T_QL + ad) = (ull)l0 | ((ull)l1 << 32);
        x = k4[idx];
        cvt2(x.x, x.y, h0, l0); cvt2(x.z, x.w, h1, l1);
        *(ull*)(sm + T_KH + ad) = (ull)h0 | ((ull)h1 << 32);
        *(ull*)(sm + T_KL + ad) = (ull)l0 | ((ull)l1 << 32);
        x = v4[idx];
        cvt2(x.x, x.y, h0, l0); cvt2(x.z, x.w, h1, l1);
        *(ull*)(sm + T_VH + ad) = (ull)h0 | ((ull)h1 << 32);
        *(ull*)(sm + T_VL + ad) = (ull)l0 | ((ull)l1 << 32);
    }
    __syncthreads();

    // ============ Phase 1: warps 0-5 -> S1=Q@K^T ; warps 6-11 -> S2=Q^T@K ====
    // warp tile 16 x 96 (full rows owned -> warp-local softmax)
    {
        float acc[12][4];
        const int m0 = (wid < 6 ? wid : wid - 6) * 16;
        const float* band;
        u32 dH, dL;
        if (wid < 6) {
            // S1[i][j] = sum_w Q[i][w] K[j][w] : A=Q norm, B=K norm
            gemm_wt<0, 0, 12>(acc, sb + T_QH, sb + T_QL, sb + T_KH, sb + T_KL, m0, 0, lane);
            band = (const float*)(sm + OFF_KH);
            dH = sb + T_A1H; dL = sb + T_A1L;
        } else {
            // S2[w][j] = sum_h Q[h][w] K[h][j] : A=Q^T (trans), B=K (trans)
            gemm_wt<1, 1, 12>(acc, sb + T_QH, sb + T_QL, sb + T_KH, sb + T_KL, m0, 0, lane);
            band = (const float*)(sm + OFF_KW);
            dH = sb + T_A2H; dL = sb + T_A2L;
        }
        // warp-local softmax over full rows + band, -> bf16 hi/lo tile
        #pragma unroll
        for (int rh = 0; rh < 2; rh++) {
            const int row = m0 + (lane >> 2) + 8 * rh;
            float mx = -1e30f;
            #pragma unroll
            for (int nt = 0; nt < 12; nt++)
                mx = fmaxf(mx, fmaxf(acc[nt][2 * rh], acc[nt][2 * rh + 1]));
            mx = fmaxf(mx, __shfl_xor_sync(0xffffffffu, mx, 1));
            mx = fmaxf(mx, __shfl_xor_sync(0xffffffffu, mx, 2));
            float s = 0.f;
            #pragma unroll
            for (int nt = 0; nt < 12; nt++)
                #pragma unroll
                for (int e = 0; e < 2; e++) {
                    float ev = __expf(acc[nt][2 * rh + e] - mx);
                    acc[nt][2 * rh + e] = ev;
                    s += ev;
                }
            s += __shfl_xor_sync(0xffffffffu, s, 1);
            s += __shfl_xor_sync(0xffffffffu, s, 2);
            const float inv = 1.0f / s;
            #pragma unroll
            for (int nt = 0; nt < 12; nt++) {
                const int col = nt * 8 + (lane & 3) * 2;
                u32 b0 = (u32)(col - row + 6), b1 = (u32)(col + 1 - row + 6);
                float x0 = fmaf(acc[nt][2 * rh + 0], inv, b0 < 13u ? band[b0] : 0.f);
                float x1 = fmaf(acc[nt][2 * rh + 1], inv, b1 < 13u ? band[b1] : 0.f);
                u32 h, l;
                cvt2(x0, x1, h, l);
                const u32 ad = (u32)(row * RSB + col * 2);
                *(u32*)((char*)sm + (dH - sb) + ad) = h;
                *(u32*)((char*)sm + (dL - sb) + ad) = l;
            }
        }
    }
    __syncthreads();

    // ============ Phase 2: GEMM2 V1 = A1 @ V  (all 12 warps, tile 16x48) =====
    // V1[i][w] = sum_j A1[i][j] V[j][w] : A=A1 norm, B=V trans
    const int m0b = (wid >> 1) * 16;
    const int n0b = (wid & 1) * 48;
    {
        float acc[6][4];
        gemm_wt<0, 1, 6>(acc, sb + T_A1H, sb + T_A1L, sb + T_VH, sb + T_VL, m0b, n0b, lane);
        // write V1 into dead Q tiles (no hazard: different buffers)
        #pragma unroll
        for (int rh = 0; rh < 2; rh++) {
            const int row = m0b + (lane >> 2) + 8 * rh;
            #pragma unroll
            for (int nt = 0; nt < 6; nt++) {
                const int col = n0b + nt * 8 + (lane & 3) * 2;
                u32 h, l;
                cvt2(acc[nt][2 * rh + 0], acc[nt][2 * rh + 1], h, l);
                const u32 ad = (u32)(row * RSB + col * 2);
                *(u32*)(sm + T_V1H + ad) = h;
                *(u32*)(sm + T_V1L + ad) = l;
            }
        }
    }
    __syncthreads();

    // ============ Phase 3: GEMM4 Out = V1 @ A2^T  (tile 16x48) ===============
    // Out[h][w] = sum_j V1[h][j] A2[w][j] : A=V1 norm, B=A2 norm
    {
        float acc[6][4];
        gemm_wt<0, 0, 6>(acc, sb + T_V1H, sb + T_V1L, sb + T_A2H, sb + T_A2L, m0b, n0b, lane);
        float* op = gout + base;
        #pragma unroll
        for (int rh = 0; rh < 2; rh++) {
            const int row = m0b + (lane >> 2) + 8 * rh;
            #pragma unroll
            for (int nt = 0; nt < 6; nt++) {
                const int col = n0b + nt * 8 + (lane & 3) * 2;
                *(float2*)(op + row * HW + col) =
                    make_float2(acc[nt][2 * rh + 0], acc[nt][2 * rh + 1]);
            }
        }
    }
}

extern "C" void kernel_launch(void* const* d_in, const int* in_sizes, int n_in,
                              void* d_out, int out_size)
{
    const float* q  = (const float*)d_in[0];
    const float* k  = (const float*)d_in[1];
    const float* v  = (const float*)d_in[2];
    const float* kh = (const float*)d_in[3];
    const float* kw = (const float*)d_in[4];
    float* out = (float*)d_out;

    const int slices = in_sizes[0] / (HW * HW);   // B*C = 2048
    const int C      = in_sizes[3] / 13;          // 256

    cudaFuncSetAttribute(axial_attn_hmma2,
                         cudaFuncAttributeMaxDynamicSharedMemorySize, SMEM_TOTAL);
    axial_attn_hmma2<<<slices, TPB, SMEM_TOTAL>>>(q, k, v, kh, kw, out, C);
}

// round 10
// speedup vs baseline: 2.3298x; 1.1123x over previous
#include <cuda_runtime.h>
#include <cuda_bf16.h>

typedef unsigned int u32;
typedef unsigned long long ull;

#define HW   96
#define TPB  384
#define LDB  104              // bf16 elems per tile row (stride 208 B, conflict-free ldmatrix)
#define RSB  (LDB * 2)        // 208 bytes
#define TILE_B (HW * RSB)     // 19968 B per tile

// ---- smem byte offsets ----
#define OFF_KH   0            // 13 floats
#define OFF_KW   64           // 13 floats
#define T_BASE   128
#define T_QH   (T_BASE + 0 * TILE_B)
#define T_QL   (T_BASE + 1 * TILE_B)
#define T_KH   (T_BASE + 2 * TILE_B)
#define T_KL   (T_BASE + 3 * TILE_B)
#define T_VH   (T_BASE + 4 * TILE_B)
#define T_VL   (T_BASE + 5 * TILE_B)
#define T_A1H  (T_BASE + 6 * TILE_B)
#define T_A1L  (T_BASE + 7 * TILE_B)
#define T_A2H  (T_BASE + 8 * TILE_B)
#define T_A2L  (T_BASE + 9 * TILE_B)
#define SMEM_TOTAL (T_BASE + 10 * TILE_B)   // 199808 B
// V1 reuses Q tiles (Q dead after GEMM3):
#define T_V1H T_QH
#define T_V1L T_QL

// ---------------- PTX wrappers ----------------
__device__ __forceinline__ u32 s2u(const void* p) {
    u32 a;
    asm("{ .reg .u64 t; cvta.to.shared.u64 t, %1; cvt.u32.u64 %0, t; }" : "=r"(a) : "l"(p));
    return a;
}
template<int TR>
__device__ __forceinline__ void ldsm4(u32 addr, u32* r) {
    if (TR)
        asm volatile("ldmatrix.sync.aligned.m8n8.x4.trans.shared.b16 {%0,%1,%2,%3}, [%4];"
                     : "=r"(r[0]), "=r"(r[1]), "=r"(r[2]), "=r"(r[3]) : "r"(addr));
    else
        asm volatile("ldmatrix.sync.aligned.m8n8.x4.shared.b16 {%0,%1,%2,%3}, [%4];"
                     : "=r"(r[0]), "=r"(r[1]), "=r"(r[2]), "=r"(r[3]) : "r"(addr));
}
__device__ __forceinline__ void mma16816(float* c, const u32* a, const u32* b) {
    asm volatile("mma.sync.aligned.m16n8k16.row.col.f32.bf16.bf16.f32 "
                 "{%0,%1,%2,%3}, {%4,%5,%6,%7}, {%8,%9}, {%0,%1,%2,%3};"
                 : "+f"(c[0]), "+f"(c[1]), "+f"(c[2]), "+f"(c[3])
                 : "r"(a[0]), "r"(a[1]), "r"(a[2]), "r"(a[3]), "r"(b[0]), "r"(b[1]));
}

// ---- hi/lo bf16 split: pack pair (x0,x1) -> hi u32, lo u32 (2x cvt.bf16x2) ----
__device__ __forceinline__ void cvt2(float x0, float x1, u32& h, u32& l) {
    asm("cvt.rn.bf16x2.f32 %0, %1, %2;" : "=r"(h) : "f"(x1), "f"(x0));
    float h0 = __uint_as_float(h << 16);
    float h1 = __uint_as_float(h & 0xffff0000u);
    asm("cvt.rn.bf16x2.f32 %0, %1, %2;" : "=r"(l) : "f"(x1 - h1), "f"(x0 - h0));
}

// ---------------- warp-tile GEMM: 16 x (8*NT) x 96, BF16x3 split ----------------
// TA/TB: operand accessed transposed via ldmatrix.trans from row-major tile.
// acc += Ah*Bh + Al*Bh + Ah*Bl
// Pass order hides Bl's ldsm latency behind the Al*Bh pass.
template<int TA, int TB, int NT>
__device__ __forceinline__ void gemm_wt(float acc[NT][4],
                                        u32 aH, u32 aL, u32 bH, u32 bL,
                                        int m0, int n0, int lane)
{
    #pragma unroll
    for (int nt = 0; nt < NT; nt++)
        #pragma unroll
        for (int e = 0; e < 4; e++) acc[nt][e] = 0.f;

    // base fragment addresses at kk = 0, then advance by constant per k-step
    u32 aad;
    {
        int ra, ca;
        if (TA) { ra = (lane & 7) + ((lane >> 4) & 1) * 8; ca = m0 + ((lane >> 3) & 1) * 8; }
        else    { ra = m0 + (lane & 7) + ((lane >> 3) & 1) * 8; ca = ((lane >> 4) & 1) * 8; }
        aad = (u32)(ra * RSB + ca * 2);
    }
    const u32 astep = TA ? (u32)(16 * RSB) : 32u;

    u32 bad[NT / 2];
    #pragma unroll
    for (int p = 0; p < NT / 2; p++) {
        int rb, cb;
        if (TB) { rb = (lane & 7) + ((lane >> 3) & 1) * 8; cb = n0 + p * 16 + ((lane >> 4) & 1) * 8; }
        else    { rb = n0 + p * 16 + (lane & 7) + ((lane >> 4) & 1) * 8; cb = ((lane >> 3) & 1) * 8; }
        bad[p] = (u32)(rb * RSB + cb * 2);
    }
    const u32 bstep = TB ? (u32)(16 * RSB) : 32u;

    #pragma unroll
    for (int kk = 0; kk < HW; kk += 16) {
        u32 Ah[4], Al[4];
        ldsm4<TA>(aH + aad, Ah);
        ldsm4<TA>(aL + aad, Al);

        u32 Bh[NT][2], Bl[NT][2];
        #pragma unroll
        for (int p = 0; p < NT / 2; p++) {
            u32 t[4];
            ldsm4<TB>(bH + bad[p], t);
            Bh[2 * p][0] = t[0]; Bh[2 * p][1] = t[1];
            Bh[2 * p + 1][0] = t[2]; Bh[2 * p + 1][1] = t[3];
        }
        // pass 1: Ah * Bh
        #pragma unroll
        for (int nt = 0; nt < NT; nt++) mma16816(acc[nt], Ah, Bh[nt]);
        // issue Bl loads; latency covered by pass 2
        #pragma unroll
        for (int p = 0; p < NT / 2; p++) {
            u32 t[4];
            ldsm4<TB>(bL + bad[p], t);
            Bl[2 * p][0] = t[0]; Bl[2 * p][1] = t[1];
            Bl[2 * p + 1][0] = t[2]; Bl[2 * p + 1][1] = t[3];
        }
        // pass 2: Al * Bh
        #pragma unroll
        for (int nt = 0; nt < NT; nt++) mma16816(acc[nt], Al, Bh[nt]);
        // pass 3: Ah * Bl
        #pragma unroll
        for (int nt = 0; nt < NT; nt++) mma16816(acc[nt], Ah, Bl[nt]);

        aad += astep;
        #pragma unroll
        for (int p = 0; p < NT / 2; p++) bad[p] += bstep;
    }
}

__global__ void __launch_bounds__(TPB, 1)
axial_attn_hmma3(const float* __restrict__ gq, const float* __restrict__ gk,
                 const float* __restrict__ gv, const float* __restrict__ gkh,
                 const float* __restrict__ gkw, float* __restrict__ gout, int C)
{
    extern __shared__ char sm[];
    const u32 sb = s2u(sm);
    const int tid  = threadIdx.x;
    const int lane = tid & 31;
    const int wid  = tid >> 5;        // 0..11

    const int slice = blockIdx.x;
    const int c = slice - (slice / C) * C;
    const size_t base = (size_t)slice * (HW * HW);

    if (tid < 13) {
        ((float*)(sm + OFF_KH))[tid] = gkh[c * 13 + tid];
        ((float*)(sm + OFF_KW))[tid] = gkw[c * 13 + tid];
    }

    // ---- load + hi/lo convert Q, K, V (row-major, stride 104 bf16) ----
    const float4* q4 = (const float4*)(gq + base);
    const float4* k4 = (const float4*)(gk + base);
    const float4* v4 = (const float4*)(gv + base);
    #pragma unroll
    for (int it = 0; it < 6; it++) {
        int idx = tid + it * TPB;               // 0..2303
        int r   = idx / 24;
        int c4  = (idx - r * 24) * 4;
        u32 ad  = (u32)(r * RSB + c4 * 2);
        u32 h0, l0, h1, l1;
        float4 x;
        x = q4[idx];
        cvt2(x.x, x.y, h0, l0); cvt2(x.z, x.w, h1, l1);
        *(ull*)(sm + T_QH + ad) = (ull)h0 | ((ull)h1 << 32);
        *(ull*)(sm + T_QL + ad) = (ull)l0 | ((ull)l1 << 32);
        x = k4[idx];
        cvt2(x.x, x.y, h0, l0); cvt2(x.z, x.w, h1, l1);
        *(ull*)(sm + T_KH + ad) = (ull)h0 | ((ull)h1 << 32);
        *(ull*)(sm + T_KL + ad) = (ull)l0 | ((ull)l1 << 32);
        x = v4[idx];
        cvt2(x.x, x.y, h0, l0); cvt2(x.z, x.w, h1, l1);
        *(ull*)(sm + T_VH + ad) = (ull)h0 | ((ull)h1 << 32);
        *(ull*)(sm + T_VL + ad) = (ull)l0 | ((ull)l1 << 32);
    }
    __syncthreads();

    // ============ Phase 1: warps 0-5 -> S1=Q@K^T ; warps 6-11 -> S2=Q^T@K ====
    // warp tile 16 x 96 (full rows owned -> warp-local softmax)
    {
        float acc[12][4];
        const int m0 = (wid < 6 ? wid : wid - 6) * 16;
        const float* band;
        u32 dH, dL;
        if (wid < 6) {
            // S1[i][j] = sum_w Q[i][w] K[j][w] : A=Q norm, B=K norm
            gemm_wt<0, 0, 12>(acc, sb + T_QH, sb + T_QL, sb + T_KH, sb + T_KL, m0, 0, lane);
            band = (const float*)(sm + OFF_KH);
            dH = sb + T_A1H; dL = sb + T_A1L;
        } else {
            // S2[w][j] = sum_h Q[h][w] K[h][j] : A=Q^T (trans), B=K (trans)
            gemm_wt<1, 1, 12>(acc, sb + T_QH, sb + T_QL, sb + T_KH, sb + T_KL, m0, 0, lane);
            band = (const float*)(sm + OFF_KW);
            dH = sb + T_A2H; dL = sb + T_A2L;
        }
        // warp-local softmax over full rows + band, -> bf16 hi/lo tile
        #pragma unroll
        for (int rh = 0; rh < 2; rh++) {
            const int row = m0 + (lane >> 2) + 8 * rh;
            float mx = -1e30f;
            #pragma unroll
            for (int nt = 0; nt < 12; nt++)
                mx = fmaxf(mx, fmaxf(acc[nt][2 * rh], acc[nt][2 * rh + 1]));
            mx = fmaxf(mx, __shfl_xor_sync(0xffffffffu, mx, 1));
            mx = fmaxf(mx, __shfl_xor_sync(0xffffffffu, mx, 2));
            float s = 0.f;
            #pragma unroll
            for (int nt = 0; nt < 12; nt++)
                #pragma unroll
                for (int e = 0; e < 2; e++) {
                    float ev = __expf(acc[nt][2 * rh + e] - mx);
                    acc[nt][2 * rh + e] = ev;
                    s += ev;
                }
            s += __shfl_xor_sync(0xffffffffu, s, 1);
            s += __shfl_xor_sync(0xffffffffu, s, 2);
            const float inv = 1.0f / s;
            #pragma unroll
            for (int nt = 0; nt < 12; nt++) {
                const int col = nt * 8 + (lane & 3) * 2;
                u32 b0 = (u32)(col - row + 6), b1 = (u32)(col + 1 - row + 6);
                float x0 = fmaf(acc[nt][2 * rh + 0], inv, b0 < 13u ? band[b0] : 0.f);
                float x1 = fmaf(acc[nt][2 * rh + 1], inv, b1 < 13u ? band[b1] : 0.f);
                u32 h, l;
                cvt2(x0, x1, h, l);
                const u32 ad = (u32)(row * RSB + col * 2);
                *(u32*)((char*)sm + (dH - sb) + ad) = h;
                *(u32*)((char*)sm + (dL - sb) + ad) = l;
            }
        }
    }
    __syncthreads();

    // ============ Phase 2: GEMM2 V1 = A1 @ V  (all 12 warps, tile 16x48) =====
    // V1[i][w] = sum_j A1[i][j] V[j][w] : A=A1 norm, B=V trans
    const int m0b = (wid >> 1) * 16;
    const int n0b = (wid & 1) * 48;
    {
        float acc[6][4];
        gemm_wt<0, 1, 6>(acc, sb + T_A1H, sb + T_A1L, sb + T_VH, sb + T_VL, m0b, n0b, lane);
        // write V1 into dead Q tiles (no hazard: different buffers)
        #pragma unroll
        for (int rh = 0; rh < 2; rh++) {
            const int row = m0b + (lane >> 2) + 8 * rh;
            #pragma unroll
            for (int nt = 0; nt < 6; nt++) {
                const int col = n0b + nt * 8 + (lane & 3) * 2;
                u32 h, l;
                cvt2(acc[nt][2 * rh + 0], acc[nt][2 * rh + 1], h, l);
                const u32 ad = (u32)(row * RSB + col * 2);
                *(u32*)(sm + T_V1H + ad) = h;
                *(u32*)(sm + T_V1L + ad) = l;
            }
        }
    }
    __syncthreads();

    // ============ Phase 3: GEMM4 Out = V1 @ A2^T  (tile 16x48) ===============
    // Out[h][w] = sum_j V1[h][j] A2[w][j] : A=V1 norm, B=A2 norm
    {
        float acc[6][4];
        gemm_wt<0, 0, 6>(acc, sb + T_V1H, sb + T_V1L, sb + T_A2H, sb + T_A2L, m0b, n0b, lane);
        float* op = gout + base;
        #pragma unroll
        for (int rh = 0; rh < 2; rh++) {
            const int row = m0b + (lane >> 2) + 8 * rh;
            #pragma unroll
            for (int nt = 0; nt < 6; nt++) {
                const int col = n0b + nt * 8 + (lane & 3) * 2;
                *(float2*)(op + row * HW + col) =
                    make_float2(acc[nt][2 * rh + 0], acc[nt][2 * rh + 1]);
            }
        }
    }
}

extern "C" void kernel_launch(void* const* d_in, const int* in_sizes, int n_in,
                              void* d_out, int out_size)
{
    const float* q  = (const float*)d_in[0];
    const float* k  = (const float*)d_in[1];
    const float* v  = (const float*)d_in[2];
    const float* kh = (const float*)d_in[3];
    const float* kw = (const float*)d_in[4];
    float* out = (float*)d_out;

    const int slices = in_sizes[0] / (HW * HW);   // B*C = 2048
    const int C      = in_sizes[3] / 13;          // 256

    cudaFuncSetAttribute(axial_attn_hmma3,
                         cudaFuncAttributeMaxDynamicSharedMemorySize, SMEM_TOTAL);
    axial_attn_hmma3<<<slices, TPB, SMEM_TOTAL>>>(q, k, v, kh, kw, out, C);
}